// round 13
// baseline (speedup 1.0000x reference)
#include <cuda_runtime.h>
#include <cuda_bf16.h>
#include <cuda_fp16.h>
#include <math.h>
#include <stdint.h>

#define T_SEQ 2048
#define B_BATCH 2
#define D_MODEL 1024
#define H_HEADS 16
#define M_ROWS 4096          /* B*T */
#define QKV_LD 3072

// ---------------------------------------------------------------------------
// Scratch (static __device__ — no allocations allowed anywhere)
// ---------------------------------------------------------------------------
__device__ __half g_qkvf[(size_t)M_ROWS * QKV_LD];   // fp16 qkv (rope + log2-scale)
__device__ __half g_xh[(size_t)M_ROWS * D_MODEL];    // x fp16
__device__ __half g_aoh[(size_t)M_ROWS * D_MODEL];   // attn out fp16
__device__ __half g_wqt[(size_t)QKV_LD * D_MODEL];   // Wqkv^T fp16
__device__ __half g_wot[(size_t)D_MODEL * D_MODEL];  // Wout^T fp16
__device__ float g_cos[T_SEQ * 32];
__device__ float g_sin[T_SEQ * 32];

// 0.125 * log2(e): folds softmax base-2 conversion into the Q scale
#define QSCALE 0.18033688011112042f

// ---------------------------------------------------------------------------
// Helpers
// ---------------------------------------------------------------------------
__device__ __forceinline__ uint32_t smem_u32(const void* p) {
    uint32_t a;
    asm("{ .reg .u64 t; cvta.to.shared.u64 t, %1; cvt.u32.u64 %0, t; }"
        : "=r"(a) : "l"(p));
    return a;
}

#define CP16(dst, src)                                                       \
    asm volatile("cp.async.cg.shared.global [%0], [%1], 16;"                 \
        :: "r"(dst), "l"(src))
#define CP_COMMIT() asm volatile("cp.async.commit_group;" ::: "memory")
#define CP_WAIT0()  asm volatile("cp.async.wait_group 0;" ::: "memory")
#define CP_WAIT1()  asm volatile("cp.async.wait_group 1;" ::: "memory")
#define CP_WAIT2()  asm volatile("cp.async.wait_group 2;" ::: "memory")

#define LDSM_X4(r, addr)                                                     \
    asm volatile("ldmatrix.sync.aligned.m8n8.x4.shared.b16 {%0,%1,%2,%3}, [%4];" \
        : "=r"((r)[0]), "=r"((r)[1]), "=r"((r)[2]), "=r"((r)[3])             \
        : "r"(addr))

#define LDSM_X4_T(r, addr)                                                   \
    asm volatile("ldmatrix.sync.aligned.m8n8.x4.trans.shared.b16 {%0,%1,%2,%3}, [%4];" \
        : "=r"((r)[0]), "=r"((r)[1]), "=r"((r)[2]), "=r"((r)[3])             \
        : "r"(addr))

#define MMA16816H(c, a, b)                                                   \
    asm volatile("mma.sync.aligned.m16n8k16.row.col.f32.f16.f16.f32 "        \
        "{%0,%1,%2,%3}, {%4,%5,%6,%7}, {%8,%9}, {%0,%1,%2,%3};"              \
        : "+f"((c)[0]), "+f"((c)[1]), "+f"((c)[2]), "+f"((c)[3])             \
        : "r"((a)[0]), "r"((a)[1]), "r"((a)[2]), "r"((a)[3]),                \
          "r"((b)[0]), "r"((b)[1]))

__device__ __forceinline__ uint32_t packh(float a, float b) {
    __half2 t = __floats2half2_rn(a, b);
    return *(uint32_t*)&t;
}

// ---------------------------------------------------------------------------
// Fused prep: RoPE tables | x -> fp16 | transpose Wqkv | transpose Wout
// ---------------------------------------------------------------------------
__global__ __launch_bounds__(256) void prep_kernel(
    const float* __restrict__ x, const float* __restrict__ Wqkv,
    const float* __restrict__ Wout)
{
    __shared__ float t[32][33];
    const int bx = blockIdx.x, tid = threadIdx.x;

    if (bx < 256) {                       // RoPE tables
        int i = bx * 256 + tid;
        int tt = i >> 5, m = i & 31;
        double invf = exp(-(double)(2 * m) * (log(10000.0) / 64.0));
        double ph = (double)tt * invf;
        g_cos[i] = (float)cos(ph);
        g_sin[i] = (float)sin(ph);
        return;
    }
    if (bx < 4352) {                      // x -> fp16
        int i = (bx - 256) * 256 + tid;   // float4 index, n4 = 1M
        float4 v = ((const float4*)x)[i];
        ((uint32_t*)g_xh)[i * 2 + 0] = packh(v.x, v.y);
        ((uint32_t*)g_xh)[i * 2 + 1] = packh(v.z, v.w);
        return;
    }
    // transpose W[K][N] fp32 -> T[N][K] fp16
    const float* W;
    __half* th;
    int N, tile, ntx;
    if (bx < 7424) { W = Wqkv; th = g_wqt; N = QKV_LD;  tile = bx - 4352; ntx = 96; }
    else           { W = Wout; th = g_wot; N = D_MODEL; tile = bx - 7424; ntx = 32; }
    const int K = D_MODEL;
    int n0 = (tile % ntx) * 32, k0 = (tile / ntx) * 32;
    int tx = tid & 31, ty = tid >> 5;
    for (int r = ty; r < 32; r += 8)
        t[r][tx] = W[(size_t)(k0 + r) * N + n0 + tx];
    __syncthreads();
    for (int r = ty; r < 32; r += 8)
        th[(size_t)(n0 + r) * K + k0 + tx] = __float2half_rn(t[tx][r]);
}

// ---------------------------------------------------------------------------
// Single-term fp16 GEMM, 4-stage cp.async pipeline, ONE barrier per chunk.
// C = A[M,K] @ Bt[N,K]^T.
// EPI=0: fp32 C out.  EPI=1: RoPE + log2-scale, fp16 out (QKV path).
// ---------------------------------------------------------------------------
#define ASTR 40
#define TILE_H (128 * ASTR)                    /* one 128x32 fp16 tile */
#define G_STAGE_B (2 * TILE_H * 2)             /* 20480 B per stage */
#define G_SMEM4 (4 * G_STAGE_B)                /* 81920 B */

template <int EPI>
__global__ __launch_bounds__(256, 2) void gemm_mma_kernel(
    const __half* __restrict__ Ah, const __half* __restrict__ Bh,
    float* __restrict__ C, __half* __restrict__ Cf, int N, int K)
{
    extern __shared__ __half smg[];
    const uint32_t sbase = smem_u32(smg);

    const int tid = threadIdx.x;
    const int wid = tid >> 5, lid = tid & 31;
    const int wm = (wid & 3) * 32;
    const int wn = (wid >> 2) * 64;

    const size_t aoff0 = (size_t)blockIdx.y * 128 * K;
    const size_t boff0 = (size_t)blockIdx.x * 128 * K;

    uint32_t aAddr[2];
#pragma unroll
    for (int mt = 0; mt < 2; mt++)
        aAddr[mt] = ((wm + mt * 16 + (lid & 15)) * ASTR + (lid >> 4) * 8) * 2;
    uint32_t bAddr[4];
#pragma unroll
    for (int p = 0; p < 4; p++)
        bAddr[p] = ((wn + p * 16 + (lid & 7) + (lid >> 4) * 8) * ASTR
                    + ((lid >> 3) & 1) * 8) * 2;

    const int nchunks = K >> 5;

    auto issue = [&](int c, int st) {
        const __half* srcs[2] = { Ah + aoff0 + c * 32, Bh + boff0 + c * 32 };
        const uint32_t d0 = sbase + st * G_STAGE_B;
#pragma unroll
        for (int tI = 0; tI < 2; tI++) {
#pragma unroll
            for (int it = 0; it < 2; it++) {
                int idx = tid + it * 256;
                int row = idx >> 2, kc = (idx & 3) * 8;
                CP16(d0 + (uint32_t)(tI * TILE_H + row * ASTR + kc) * 2,
                     srcs[tI] + (size_t)row * K + kc);
            }
        }
        CP_COMMIT();
    };

    float acc[2][8][4] = {};

    issue(0, 0);
    issue(1, 1);
    issue(2, 2);
    int st = 0;
    for (int c = 0; c < nchunks; c++) {
        if (c + 2 < nchunks)      CP_WAIT2();
        else if (c + 1 < nchunks) CP_WAIT1();
        else                      CP_WAIT0();
        __syncthreads();                       // stage c visible; stage of c-1 free
        if (c + 3 < nchunks) issue(c + 3, (st + 3) & 3);

        const uint32_t sAh = sbase + st * G_STAGE_B;
        const uint32_t sBh = sAh + TILE_H * 2;

#pragma unroll
        for (int ks = 0; ks < 2; ks++) {
            const uint32_t kb = ks * 32;
            uint32_t ah[2][4];
#pragma unroll
            for (int mt = 0; mt < 2; mt++)
                LDSM_X4(ah[mt], sAh + aAddr[mt] + kb);
#pragma unroll
            for (int p = 0; p < 4; p++) {
                uint32_t bh[4];
                LDSM_X4(bh, sBh + bAddr[p] + kb);
                MMA16816H(acc[0][2 * p],     ah[0], bh);
                MMA16816H(acc[1][2 * p],     ah[1], bh);
                MMA16816H(acc[0][2 * p + 1], ah[0], bh + 2);
                MMA16816H(acc[1][2 * p + 1], ah[1], bh + 2);
            }
        }
        st = (st + 1) & 3;
    }

    const int mbase = blockIdx.y * 128 + wm + (lid >> 2);
    const int nbase = blockIdx.x * 128 + wn + (lid & 3) * 2;
#pragma unroll
    for (int mt = 0; mt < 2; mt++) {
#pragma unroll
        for (int half = 0; half < 2; half++) {
            const int row = mbase + mt * 16 + half * 8;
#pragma unroll
            for (int nt = 0; nt < 8; nt++) {
                const int col = nbase + nt * 8;
                float v0 = acc[mt][nt][2 * half + 0];
                float v1 = acc[mt][nt][2 * half + 1];
                if (EPI == 0) {
                    *(float2*)(C + (size_t)row * N + col) = make_float2(v0, v1);
                } else {
                    if (col < 2048) {                  // rope on q,k
                        int t = row & (T_SEQ - 1);
                        int m0 = col & 31;
                        float c0 = g_cos[t * 32 + m0], s0 = g_sin[t * 32 + m0];
                        float c1 = g_cos[t * 32 + m0 + 1], s1 = g_sin[t * 32 + m0 + 1];
                        float o0 = v0 * c0 - v1 * s0;
                        float o1 = v1 * c1 + v0 * s1;
                        if (col < 1024) { o0 *= QSCALE; o1 *= QSCALE; }
                        v0 = o0; v1 = o1;
                    }
                    *(uint32_t*)(Cf + (size_t)row * N + col) = packh(v0, v1);
                }
            }
        }
    }
}

// ---------------------------------------------------------------------------
// fp16 mma.sync flash attention, base-2 softmax (ex2.approx.f16x2),
// 4-stage cp.async KV pipeline, ONE barrier per chunk.
// CTA: 128 q-rows x one (b,h). 8 warps x m16. K/V chunks of 64.
// ---------------------------------------------------------------------------
#define QSTR 72
#define Q_ELE (128 * QSTR)
#define KVT (64 * QSTR)
#define KV_STAGE (2 * KVT)
#define ATT_SMEM ((Q_ELE + 4 * KV_STAGE) * 2)   /* 92160 B */

__global__ __launch_bounds__(256, 2) void attn_mma_kernel(
    const __half* __restrict__ qkv, __half* __restrict__ aoh)
{
    extern __shared__ __half smh[];
    const uint32_t sb = smem_u32(smh);
    const int tid = threadIdx.x, wid = tid >> 5, lid = tid & 31;
    const int b = blockIdx.y >> 4, h = blockIdx.y & 15;
    const int q0 = blockIdx.x * 128;
    const size_t rowbase = (size_t)(b * T_SEQ) * QKV_LD;
    const int hc = h * 64;

    auto issue_kv = [&](int s0, int st) {
        const uint32_t d0 = sb + (Q_ELE + st * KV_STAGE) * 2;
#pragma unroll
        for (int i = 0; i < 2; i++) {
            int idx = tid + i * 256;
            int r = idx >> 3, c8 = (idx & 7) * 8;
            size_t gk = rowbase + (size_t)(s0 + r) * QKV_LD + 1024 + hc + c8;
            uint32_t so = (uint32_t)(r * QSTR + c8) * 2;
            CP16(d0 + so,           qkv + gk);          // K
            CP16(d0 + KVT * 2 + so, qkv + gk + 1024);   // V
        }
        CP_COMMIT();
    };

    // Prologue: group0 = Q + KV chunk 0; groups 1,2 = KV chunks 1,2
    {
#pragma unroll
        for (int i = 0; i < 4; i++) {
            int idx = tid + i * 256;
            int r = idx >> 3, c8 = (idx & 7) * 8;
            size_t g = rowbase + (size_t)(q0 + r) * QKV_LD + hc + c8;
            CP16(sb + (uint32_t)(r * QSTR + c8) * 2, qkv + g);
        }
        issue_kv(0, 0);
        issue_kv(64, 1);
        issue_kv(128, 2);
    }

    const int wm = wid * 16;
    const uint32_t qAddr = sb + ((wm + (lid & 15)) * QSTR + (lid >> 4) * 8) * 2;
    const uint32_t kRel = (((lid & 7) + (lid >> 4) * 8) * QSTR + ((lid >> 3) & 1) * 8) * 2;
    const uint32_t vRel = ((lid & 15) * QSTR + (lid >> 4) * 8) * 2;

    float o[8][4] = {};
    float mrow[2] = {-INFINITY, -INFINITY};   // log2 domain
    float lrow[2] = {0.f, 0.f};

    const int nchunks = T_SEQ / 64;
    int st = 0;
    for (int c = 0; c < nchunks; c++) {
        if (c + 2 < nchunks)      CP_WAIT2();
        else if (c + 1 < nchunks) CP_WAIT1();
        else                      CP_WAIT0();
        __syncthreads();
        if (c + 3 < nchunks) issue_kv((c + 3) * 64, (st + 3) & 3);

        const uint32_t kBase = sb + (Q_ELE + st * KV_STAGE) * 2 + kRel;
        const uint32_t vBase = sb + (Q_ELE + st * KV_STAGE + KVT) * 2 + vRel;

        // S = Q K^T  (S in log2 domain: Q carries 0.125*log2e)
        float sc[8][4] = {};
#pragma unroll
        for (int ks = 0; ks < 4; ks++) {
            uint32_t ah[4];
            LDSM_X4(ah, qAddr + ks * 32);
#pragma unroll
            for (int p = 0; p < 4; p++) {
                uint32_t bh[4];
                LDSM_X4(bh, kBase + p * (16 * QSTR * 2) + ks * 32);
                MMA16816H(sc[2 * p],     ah, bh);
                MMA16816H(sc[2 * p + 1], ah, bh + 2);
            }
        }

        // Base-2 online softmax, P computed as ex2.approx.f16x2(s - m)
        uint32_t ph[4][4];
#pragma unroll
        for (int hr = 0; hr < 2; hr++) {
            float mx = -INFINITY;
#pragma unroll
            for (int t = 0; t < 8; t++)
                mx = fmaxf(mx, fmaxf(sc[t][2 * hr], sc[t][2 * hr + 1]));
            mx = fmaxf(mx, __shfl_xor_sync(0xffffffffu, mx, 1));
            mx = fmaxf(mx, __shfl_xor_sync(0xffffffffu, mx, 2));
            float mnew = fmaxf(mrow[hr], mx);
            float alpha = exp2f(mrow[hr] - mnew);

            __half2 e[8];
#pragma unroll
            for (int t = 0; t < 8; t++) {
                e[t] = h2exp2(__floats2half2_rn(sc[t][2 * hr] - mnew,
                                                sc[t][2 * hr + 1] - mnew));
                ph[t >> 1][(t & 1) * 2 + hr] = *(uint32_t*)&e[t];
            }
            float rs = 0.f;
#pragma unroll
            for (int t = 0; t < 8; t += 2) {
                float2 f2 = __half22float2(__hadd2(e[t], e[t + 1]));
                rs += f2.x + f2.y;
            }
            rs += __shfl_xor_sync(0xffffffffu, rs, 1);
            rs += __shfl_xor_sync(0xffffffffu, rs, 2);
            lrow[hr] = lrow[hr] * alpha + rs;
            // Warp-uniform skip: when no lane's max moved, alpha==1 for all.
            if (!__all_sync(0xffffffffu, mnew == mrow[hr])) {
#pragma unroll
                for (int t = 0; t < 8; t++) {
                    o[t][2 * hr] *= alpha;
                    o[t][2 * hr + 1] *= alpha;
                }
            }
            mrow[hr] = mnew;
        }

        // O += P V
#pragma unroll
        for (int ks = 0; ks < 4; ks++) {
#pragma unroll
            for (int p = 0; p < 4; p++) {
                uint32_t vh[4];
                LDSM_X4_T(vh, vBase + ks * (16 * QSTR * 2) + p * 32);
                MMA16816H(o[2 * p],     ph[ks], vh);
                MMA16816H(o[2 * p + 1], ph[ks], vh + 2);
            }
        }
        st = (st + 1) & 3;
    }

    // Normalize + fp16 store
#pragma unroll
    for (int hr = 0; hr < 2; hr++) {
        int r = q0 + wm + (lid >> 2) + hr * 8;
        float inv = 1.0f / lrow[hr];
        size_t rowoff = (size_t)(b * T_SEQ + r) * D_MODEL + hc + (lid & 3) * 2;
#pragma unroll
        for (int t = 0; t < 8; t++)
            *(uint32_t*)(aoh + rowoff + t * 8) =
                packh(o[t][2 * hr] * inv, o[t][2 * hr + 1] * inv);
    }
}

// ---------------------------------------------------------------------------
// Launch
// ---------------------------------------------------------------------------
extern "C" void kernel_launch(void* const* d_in, const int* in_sizes, int n_in,
                              void* d_out, int out_size) {
    const float* x    = (const float*)d_in[0];
    const float* Wqkv = (const float*)d_in[1];
    const float* Wout = (const float*)d_in[2];
    float* out = (float*)d_out;

    __half *qkvf, *xh, *aoh, *wq, *wo;
    cudaGetSymbolAddress((void**)&qkvf, g_qkvf);
    cudaGetSymbolAddress((void**)&xh, g_xh);
    cudaGetSymbolAddress((void**)&aoh, g_aoh);
    cudaGetSymbolAddress((void**)&wq, g_wqt);
    cudaGetSymbolAddress((void**)&wo, g_wot);

    cudaFuncSetAttribute((const void*)gemm_mma_kernel<0>,
                         cudaFuncAttributeMaxDynamicSharedMemorySize, G_SMEM4);
    cudaFuncSetAttribute((const void*)gemm_mma_kernel<1>,
                         cudaFuncAttributeMaxDynamicSharedMemorySize, G_SMEM4);
    cudaFuncSetAttribute((const void*)attn_mma_kernel,
                         cudaFuncAttributeMaxDynamicSharedMemorySize, ATT_SMEM);

    // 1. Fused prep: tables | x->fp16 | W transposes
    prep_kernel<<<8448, 256>>>(x, Wqkv, Wout);

    // 2. QKV projection (fp16) + fused RoPE/log2-scale epilogue
    gemm_mma_kernel<1><<<dim3(QKV_LD / 128, M_ROWS / 128), 256, G_SMEM4>>>(
        xh, wq, nullptr, qkvf, QKV_LD, D_MODEL);

    // 3. Attention (fp16 mma.sync flash, base-2 softmax)
    attn_mma_kernel<<<dim3(T_SEQ / 128, B_BATCH * H_HEADS), 256, ATT_SMEM>>>(
        qkvf, aoh);

    // 4. Output projection (fp16)
    gemm_mma_kernel<0><<<dim3(D_MODEL / 128, M_ROWS / 128), 256, G_SMEM4>>>(
        aoh, wo, out, nullptr, D_MODEL, D_MODEL);
}

// round 16
// speedup vs baseline: 1.0099x; 1.0099x over previous
#include <cuda_runtime.h>
#include <cuda_bf16.h>
#include <cuda_fp16.h>
#include <math.h>
#include <stdint.h>

#define T_SEQ 2048
#define B_BATCH 2
#define D_MODEL 1024
#define H_HEADS 16
#define M_ROWS 4096          /* B*T */
#define QKV_LD 3072

// ---------------------------------------------------------------------------
// Scratch (static __device__ — no allocations allowed anywhere)
// ---------------------------------------------------------------------------
__device__ __half g_qkvf[(size_t)M_ROWS * QKV_LD];   // fp16 qkv (rope + log2-scale)
__device__ __half g_xh[(size_t)M_ROWS * D_MODEL];    // x fp16
__device__ __half g_aoh[(size_t)M_ROWS * D_MODEL];   // attn out fp16
__device__ __half g_wqt[(size_t)QKV_LD * D_MODEL];   // Wqkv^T fp16
__device__ __half g_wot[(size_t)D_MODEL * D_MODEL];  // Wout^T fp16
__device__ float g_cos[T_SEQ * 32];
__device__ float g_sin[T_SEQ * 32];

// 0.125 * log2(e): folds softmax base-2 conversion into the Q scale
#define QSCALE 0.18033688011112042f

// ---------------------------------------------------------------------------
// Helpers
// ---------------------------------------------------------------------------
__device__ __forceinline__ uint32_t smem_u32(const void* p) {
    uint32_t a;
    asm("{ .reg .u64 t; cvta.to.shared.u64 t, %1; cvt.u32.u64 %0, t; }"
        : "=r"(a) : "l"(p));
    return a;
}

#define CP16(dst, src)                                                       \
    asm volatile("cp.async.cg.shared.global [%0], [%1], 16;"                 \
        :: "r"(dst), "l"(src))
#define CP_COMMIT() asm volatile("cp.async.commit_group;" ::: "memory")
#define CP_WAIT0()  asm volatile("cp.async.wait_group 0;" ::: "memory")
#define CP_WAIT1()  asm volatile("cp.async.wait_group 1;" ::: "memory")
#define CP_WAIT2()  asm volatile("cp.async.wait_group 2;" ::: "memory")

#define LDSM_X4(r, addr)                                                     \
    asm volatile("ldmatrix.sync.aligned.m8n8.x4.shared.b16 {%0,%1,%2,%3}, [%4];" \
        : "=r"((r)[0]), "=r"((r)[1]), "=r"((r)[2]), "=r"((r)[3])             \
        : "r"(addr))

#define LDSM_X4_T(r, addr)                                                   \
    asm volatile("ldmatrix.sync.aligned.m8n8.x4.trans.shared.b16 {%0,%1,%2,%3}, [%4];" \
        : "=r"((r)[0]), "=r"((r)[1]), "=r"((r)[2]), "=r"((r)[3])             \
        : "r"(addr))

#define MMA16816H(c, a, b)                                                   \
    asm volatile("mma.sync.aligned.m16n8k16.row.col.f32.f16.f16.f32 "        \
        "{%0,%1,%2,%3}, {%4,%5,%6,%7}, {%8,%9}, {%0,%1,%2,%3};"              \
        : "+f"((c)[0]), "+f"((c)[1]), "+f"((c)[2]), "+f"((c)[3])             \
        : "r"((a)[0]), "r"((a)[1]), "r"((a)[2]), "r"((a)[3]),                \
          "r"((b)[0]), "r"((b)[1]))

__device__ __forceinline__ uint32_t packh(float a, float b) {
    __half2 t = __floats2half2_rn(a, b);
    return *(uint32_t*)&t;
}

// ---------------------------------------------------------------------------
// Fused prep: RoPE tables | x -> fp16 | transpose Wqkv | transpose Wout
// ---------------------------------------------------------------------------
__global__ __launch_bounds__(256) void prep_kernel(
    const float* __restrict__ x, const float* __restrict__ Wqkv,
    const float* __restrict__ Wout)
{
    __shared__ float t[32][33];
    const int bx = blockIdx.x, tid = threadIdx.x;

    if (bx < 256) {                       // RoPE tables
        int i = bx * 256 + tid;
        int tt = i >> 5, m = i & 31;
        double invf = exp(-(double)(2 * m) * (log(10000.0) / 64.0));
        double ph = (double)tt * invf;
        g_cos[i] = (float)cos(ph);
        g_sin[i] = (float)sin(ph);
        return;
    }
    if (bx < 4352) {                      // x -> fp16
        int i = (bx - 256) * 256 + tid;   // float4 index, n4 = 1M
        float4 v = ((const float4*)x)[i];
        ((uint32_t*)g_xh)[i * 2 + 0] = packh(v.x, v.y);
        ((uint32_t*)g_xh)[i * 2 + 1] = packh(v.z, v.w);
        return;
    }
    // transpose W[K][N] fp32 -> T[N][K] fp16
    const float* W;
    __half* th;
    int N, tile, ntx;
    if (bx < 7424) { W = Wqkv; th = g_wqt; N = QKV_LD;  tile = bx - 4352; ntx = 96; }
    else           { W = Wout; th = g_wot; N = D_MODEL; tile = bx - 7424; ntx = 32; }
    const int K = D_MODEL;
    int n0 = (tile % ntx) * 32, k0 = (tile / ntx) * 32;
    int tx = tid & 31, ty = tid >> 5;
    for (int r = ty; r < 32; r += 8)
        t[r][tx] = W[(size_t)(k0 + r) * N + n0 + tx];
    __syncthreads();
    for (int r = ty; r < 32; r += 8)
        th[(size_t)(n0 + r) * K + k0 + tx] = __float2half_rn(t[tx][r]);
}

// ---------------------------------------------------------------------------
// Single-term fp16 GEMM, 4-stage cp.async pipeline, ONE barrier per chunk,
// B-fragment prefetch (depth 1) inside the chunk.
// C = A[M,K] @ Bt[N,K]^T.
// EPI=0: fp32 C out.  EPI=1: RoPE + log2-scale, fp16 out (QKV path).
// ---------------------------------------------------------------------------
#define ASTR 40
#define TILE_H (128 * ASTR)                    /* one 128x32 fp16 tile */
#define G_STAGE_B (2 * TILE_H * 2)             /* 20480 B per stage */
#define G_SMEM4 (4 * G_STAGE_B)                /* 81920 B */

template <int EPI>
__global__ __launch_bounds__(256, 2) void gemm_mma_kernel(
    const __half* __restrict__ Ah, const __half* __restrict__ Bh,
    float* __restrict__ C, __half* __restrict__ Cf, int N, int K)
{
    extern __shared__ __half smg[];
    const uint32_t sbase = smem_u32(smg);

    const int tid = threadIdx.x;
    const int wid = tid >> 5, lid = tid & 31;
    const int wm = (wid & 3) * 32;
    const int wn = (wid >> 2) * 64;

    const size_t aoff0 = (size_t)blockIdx.y * 128 * K;
    const size_t boff0 = (size_t)blockIdx.x * 128 * K;

    uint32_t aAddr[2];
#pragma unroll
    for (int mt = 0; mt < 2; mt++)
        aAddr[mt] = ((wm + mt * 16 + (lid & 15)) * ASTR + (lid >> 4) * 8) * 2;
    uint32_t bAddr[4];
#pragma unroll
    for (int p = 0; p < 4; p++)
        bAddr[p] = ((wn + p * 16 + (lid & 7) + (lid >> 4) * 8) * ASTR
                    + ((lid >> 3) & 1) * 8) * 2;

    const int nchunks = K >> 5;

    auto issue = [&](int c, int st) {
        const __half* srcs[2] = { Ah + aoff0 + c * 32, Bh + boff0 + c * 32 };
        const uint32_t d0 = sbase + st * G_STAGE_B;
#pragma unroll
        for (int tI = 0; tI < 2; tI++) {
#pragma unroll
            for (int it = 0; it < 2; it++) {
                int idx = tid + it * 256;
                int row = idx >> 2, kc = (idx & 3) * 8;
                CP16(d0 + (uint32_t)(tI * TILE_H + row * ASTR + kc) * 2,
                     srcs[tI] + (size_t)row * K + kc);
            }
        }
        CP_COMMIT();
    };

    float acc[2][8][4] = {};

    issue(0, 0);
    issue(1, 1);
    issue(2, 2);
    int st = 0;
    for (int c = 0; c < nchunks; c++) {
        if (c + 2 < nchunks)      CP_WAIT2();
        else if (c + 1 < nchunks) CP_WAIT1();
        else                      CP_WAIT0();
        __syncthreads();
        if (c + 3 < nchunks) issue(c + 3, (st + 3) & 3);

        const uint32_t sAh = sbase + st * G_STAGE_B;
        const uint32_t sBh = sAh + TILE_H * 2;

        // Preload all A fragments for this chunk
        uint32_t ah[2][2][4];
#pragma unroll
        for (int ks = 0; ks < 2; ks++)
#pragma unroll
            for (int mt = 0; mt < 2; mt++)
                LDSM_X4(ah[ks][mt], sAh + aAddr[mt] + ks * 32);

        // B-fragment prefetch pipeline: 8 (ks,p) steps
        uint32_t bb[2][4];
        LDSM_X4(bb[0], sBh + bAddr[0]);
#pragma unroll
        for (int i = 0; i < 8; i++) {
            const int ks = i >> 2, p = i & 3, cur = i & 1;
            if (i < 7) {
                const int ni = i + 1;
                LDSM_X4(bb[cur ^ 1], sBh + bAddr[ni & 3] + (ni >> 2) * 32);
            }
            MMA16816H(acc[0][2 * p],     ah[ks][0], bb[cur]);
            MMA16816H(acc[1][2 * p],     ah[ks][1], bb[cur]);
            MMA16816H(acc[0][2 * p + 1], ah[ks][0], bb[cur] + 2);
            MMA16816H(acc[1][2 * p + 1], ah[ks][1], bb[cur] + 2);
        }
        st = (st + 1) & 3;
    }

    const int mbase = blockIdx.y * 128 + wm + (lid >> 2);
    const int nbase = blockIdx.x * 128 + wn + (lid & 3) * 2;
#pragma unroll
    for (int mt = 0; mt < 2; mt++) {
#pragma unroll
        for (int half = 0; half < 2; half++) {
            const int row = mbase + mt * 16 + half * 8;
#pragma unroll
            for (int nt = 0; nt < 8; nt++) {
                const int col = nbase + nt * 8;
                float v0 = acc[mt][nt][2 * half + 0];
                float v1 = acc[mt][nt][2 * half + 1];
                if (EPI == 0) {
                    *(float2*)(C + (size_t)row * N + col) = make_float2(v0, v1);
                } else {
                    if (col < 2048) {                  // rope on q,k
                        int t = row & (T_SEQ - 1);
                        int m0 = col & 31;
                        float c0 = g_cos[t * 32 + m0], s0 = g_sin[t * 32 + m0];
                        float c1 = g_cos[t * 32 + m0 + 1], s1 = g_sin[t * 32 + m0 + 1];
                        float o0 = v0 * c0 - v1 * s0;
                        float o1 = v1 * c1 + v0 * s1;
                        if (col < 1024) { o0 *= QSCALE; o1 *= QSCALE; }
                        v0 = o0; v1 = o1;
                    }
                    *(uint32_t*)(Cf + (size_t)row * N + col) = packh(v0, v1);
                }
            }
        }
    }
}

// ---------------------------------------------------------------------------
// fp16 mma.sync flash attention, base-2 softmax (ex2.approx.f16x2),
// 3-stage cp.async KV pipeline, Q fragments hoisted, K/V fragment prefetch.
// CTA: 128 q-rows x one (b,h). 8 warps x m16. K/V chunks of 64.
// ---------------------------------------------------------------------------
#define QSTR 72
#define Q_ELE (128 * QSTR)
#define KVT (64 * QSTR)
#define KV_STAGE (2 * KVT)
#define ATT_SMEM ((Q_ELE + 3 * KV_STAGE) * 2)   /* 73728 B */

__global__ __launch_bounds__(256, 2) void attn_mma_kernel(
    const __half* __restrict__ qkv, __half* __restrict__ aoh)
{
    extern __shared__ __half smh[];
    const uint32_t sb = smem_u32(smh);
    const int tid = threadIdx.x, wid = tid >> 5, lid = tid & 31;
    const int b = blockIdx.y >> 4, h = blockIdx.y & 15;
    const int q0 = blockIdx.x * 128;
    const size_t rowbase = (size_t)(b * T_SEQ) * QKV_LD;
    const int hc = h * 64;

    auto issue_kv = [&](int s0, int st) {
        const uint32_t d0 = sb + (Q_ELE + st * KV_STAGE) * 2;
#pragma unroll
        for (int i = 0; i < 2; i++) {
            int idx = tid + i * 256;
            int r = idx >> 3, c8 = (idx & 7) * 8;
            size_t gk = rowbase + (size_t)(s0 + r) * QKV_LD + 1024 + hc + c8;
            uint32_t so = (uint32_t)(r * QSTR + c8) * 2;
            CP16(d0 + so,           qkv + gk);          // K
            CP16(d0 + KVT * 2 + so, qkv + gk + 1024);   // V
        }
        CP_COMMIT();
    };

    // Prologue: group0 = Q + KV chunk 0; group1 = KV chunk 1
    {
#pragma unroll
        for (int i = 0; i < 4; i++) {
            int idx = tid + i * 256;
            int r = idx >> 3, c8 = (idx & 7) * 8;
            size_t g = rowbase + (size_t)(q0 + r) * QKV_LD + hc + c8;
            CP16(sb + (uint32_t)(r * QSTR + c8) * 2, qkv + g);
        }
        issue_kv(0, 0);
        issue_kv(64, 1);
    }

    const int wm = wid * 16;
    const uint32_t qAddr = sb + ((wm + (lid & 15)) * QSTR + (lid >> 4) * 8) * 2;
    const uint32_t kRel = (((lid & 7) + (lid >> 4) * 8) * QSTR + ((lid >> 3) & 1) * 8) * 2;
    const uint32_t vRel = ((lid & 15) * QSTR + (lid >> 4) * 8) * 2;

    float o[8][4] = {};
    float mrow[2] = {-INFINITY, -INFINITY};   // log2 domain
    float lrow[2] = {0.f, 0.f};

    // Hoist Q fragments: resident across the whole KV loop.
    // CP_WAIT1: wait until <=1 group pending => group0 (Q + KV0) COMPLETE.
    // (Round-14 bug: CP_WAIT2 with exactly 2 groups in flight was a no-op,
    //  so Q was read before the copy landed -> NaN.)
    uint32_t qa[4][4];
    {
        CP_WAIT1();
        __syncthreads();
#pragma unroll
        for (int ks = 0; ks < 4; ks++)
            LDSM_X4(qa[ks], qAddr + ks * 32);
    }

    const int nchunks = T_SEQ / 64;
    int st = 0;
    for (int c = 0; c < nchunks; c++) {
        if (c + 1 < nchunks) CP_WAIT1(); else CP_WAIT0();
        __syncthreads();
        if (c + 2 < nchunks) issue_kv((c + 2) * 64, (st + 2) % 3);

        const uint32_t kBase = sb + (Q_ELE + st * KV_STAGE) * 2 + kRel;
        const uint32_t vBase = sb + (Q_ELE + st * KV_STAGE + KVT) * 2 + vRel;

        // S = Q K^T  (S in log2 domain), K-fragment prefetch
        float sc[8][4] = {};
        {
            uint32_t kb[2][4];
            LDSM_X4(kb[0], kBase);
#pragma unroll
            for (int i = 0; i < 16; i++) {
                const int ks = i >> 2, p = i & 3, cur = i & 1;
                if (i < 15) {
                    const int ni = i + 1;
                    LDSM_X4(kb[cur ^ 1],
                            kBase + (ni & 3) * (16 * QSTR * 2) + (ni >> 2) * 32);
                }
                MMA16816H(sc[2 * p],     qa[ks], kb[cur]);
                MMA16816H(sc[2 * p + 1], qa[ks], kb[cur] + 2);
            }
        }

        // Base-2 online softmax, P computed as ex2.approx.f16x2(s - m)
        uint32_t ph[4][4];
#pragma unroll
        for (int hr = 0; hr < 2; hr++) {
            float mx = -INFINITY;
#pragma unroll
            for (int t = 0; t < 8; t++)
                mx = fmaxf(mx, fmaxf(sc[t][2 * hr], sc[t][2 * hr + 1]));
            mx = fmaxf(mx, __shfl_xor_sync(0xffffffffu, mx, 1));
            mx = fmaxf(mx, __shfl_xor_sync(0xffffffffu, mx, 2));
            float mnew = fmaxf(mrow[hr], mx);
            float alpha = exp2f(mrow[hr] - mnew);

            __half2 e[8];
#pragma unroll
            for (int t = 0; t < 8; t++) {
                e[t] = h2exp2(__floats2half2_rn(sc[t][2 * hr] - mnew,
                                                sc[t][2 * hr + 1] - mnew));
                ph[t >> 1][(t & 1) * 2 + hr] = *(uint32_t*)&e[t];
            }
            float rs = 0.f;
#pragma unroll
            for (int t = 0; t < 8; t += 2) {
                float2 f2 = __half22float2(__hadd2(e[t], e[t + 1]));
                rs += f2.x + f2.y;
            }
            rs += __shfl_xor_sync(0xffffffffu, rs, 1);
            rs += __shfl_xor_sync(0xffffffffu, rs, 2);
            lrow[hr] = lrow[hr] * alpha + rs;
            // Warp-uniform skip: when no lane's max moved, alpha==1 for all.
            if (!__all_sync(0xffffffffu, mnew == mrow[hr])) {
#pragma unroll
                for (int t = 0; t < 8; t++) {
                    o[t][2 * hr] *= alpha;
                    o[t][2 * hr + 1] *= alpha;
                }
            }
            mrow[hr] = mnew;
        }

        // O += P V  (V-fragment prefetch)
        {
            uint32_t vb[2][4];
            LDSM_X4_T(vb[0], vBase);
#pragma unroll
            for (int i = 0; i < 16; i++) {
                const int ks = i >> 2, p = i & 3, cur = i & 1;
                if (i < 15) {
                    const int ni = i + 1;
                    LDSM_X4_T(vb[cur ^ 1],
                              vBase + (ni >> 2) * (16 * QSTR * 2) + (ni & 3) * 32);
                }
                MMA16816H(o[2 * p],     ph[ks], vb[cur]);
                MMA16816H(o[2 * p + 1], ph[ks], vb[cur] + 2);
            }
        }
        st = (st + 1 == 3) ? 0 : st + 1;
    }

    // Normalize + fp16 store
#pragma unroll
    for (int hr = 0; hr < 2; hr++) {
        int r = q0 + wm + (lid >> 2) + hr * 8;
        float inv = 1.0f / lrow[hr];
        size_t rowoff = (size_t)(b * T_SEQ + r) * D_MODEL + hc + (lid & 3) * 2;
#pragma unroll
        for (int t = 0; t < 8; t++)
            *(uint32_t*)(aoh + rowoff + t * 8) =
                packh(o[t][2 * hr] * inv, o[t][2 * hr + 1] * inv);
    }
}

// ---------------------------------------------------------------------------
// Launch
// ---------------------------------------------------------------------------
extern "C" void kernel_launch(void* const* d_in, const int* in_sizes, int n_in,
                              void* d_out, int out_size) {
    const float* x    = (const float*)d_in[0];
    const float* Wqkv = (const float*)d_in[1];
    const float* Wout = (const float*)d_in[2];
    float* out = (float*)d_out;

    __half *qkvf, *xh, *aoh, *wq, *wo;
    cudaGetSymbolAddress((void**)&qkvf, g_qkvf);
    cudaGetSymbolAddress((void**)&xh, g_xh);
    cudaGetSymbolAddress((void**)&aoh, g_aoh);
    cudaGetSymbolAddress((void**)&wq, g_wqt);
    cudaGetSymbolAddress((void**)&wo, g_wot);

    cudaFuncSetAttribute((const void*)gemm_mma_kernel<0>,
                         cudaFuncAttributeMaxDynamicSharedMemorySize, G_SMEM4);
    cudaFuncSetAttribute((const void*)gemm_mma_kernel<1>,
                         cudaFuncAttributeMaxDynamicSharedMemorySize, G_SMEM4);
    cudaFuncSetAttribute((const void*)attn_mma_kernel,
                         cudaFuncAttributeMaxDynamicSharedMemorySize, ATT_SMEM);

    // 1. Fused prep: tables | x->fp16 | W transposes
    prep_kernel<<<8448, 256>>>(x, Wqkv, Wout);

    // 2. QKV projection (fp16) + fused RoPE/log2-scale epilogue
    gemm_mma_kernel<1><<<dim3(QKV_LD / 128, M_ROWS / 128), 256, G_SMEM4>>>(
        xh, wq, nullptr, qkvf, QKV_LD, D_MODEL);

    // 3. Attention (fp16 mma.sync flash, base-2 softmax)
    attn_mma_kernel<<<dim3(T_SEQ / 128, B_BATCH * H_HEADS), 256, ATT_SMEM>>>(
        qkvf, aoh);

    // 4. Output projection (fp16)
    gemm_mma_kernel<0><<<dim3(D_MODEL / 128, M_ROWS / 128), 256, G_SMEM4>>>(
        aoh, wo, out, nullptr, D_MODEL, D_MODEL);
}

// round 17
// speedup vs baseline: 1.0869x; 1.0763x over previous
#include <cuda_runtime.h>
#include <cuda_bf16.h>
#include <cuda_fp16.h>
#include <math.h>
#include <stdint.h>

#define T_SEQ 2048
#define B_BATCH 2
#define D_MODEL 1024
#define H_HEADS 16
#define M_ROWS 4096          /* B*T */
#define QKV_LD 3072

// ---------------------------------------------------------------------------
// Scratch (static __device__ — no allocations allowed anywhere)
// ---------------------------------------------------------------------------
__device__ __half g_qkvf[(size_t)M_ROWS * QKV_LD];   // fp16 qkv (rope + log2-scale)
__device__ __half g_xh[(size_t)M_ROWS * D_MODEL];    // x fp16
__device__ __half g_aoh[(size_t)M_ROWS * D_MODEL];   // attn out fp16
__device__ __half g_wqt[(size_t)QKV_LD * D_MODEL];   // Wqkv^T fp16
__device__ __half g_wot[(size_t)D_MODEL * D_MODEL];  // Wout^T fp16
__device__ float g_cos[T_SEQ * 32];
__device__ float g_sin[T_SEQ * 32];

// 0.125 * log2(e): folds softmax base-2 conversion into the Q scale
#define QSCALE 0.18033688011112042f

// ---------------------------------------------------------------------------
// Helpers
// ---------------------------------------------------------------------------
__device__ __forceinline__ uint32_t smem_u32(const void* p) {
    uint32_t a;
    asm("{ .reg .u64 t; cvta.to.shared.u64 t, %1; cvt.u32.u64 %0, t; }"
        : "=r"(a) : "l"(p));
    return a;
}

#define CP16(dst, src)                                                       \
    asm volatile("cp.async.cg.shared.global [%0], [%1], 16;"                 \
        :: "r"(dst), "l"(src))
#define CP_COMMIT() asm volatile("cp.async.commit_group;" ::: "memory")
#define CP_WAIT0()  asm volatile("cp.async.wait_group 0;" ::: "memory")
#define CP_WAIT1()  asm volatile("cp.async.wait_group 1;" ::: "memory")

#define LDSM_X4(r, addr)                                                     \
    asm volatile("ldmatrix.sync.aligned.m8n8.x4.shared.b16 {%0,%1,%2,%3}, [%4];" \
        : "=r"((r)[0]), "=r"((r)[1]), "=r"((r)[2]), "=r"((r)[3])             \
        : "r"(addr))

#define LDSM_X4_T(r, addr)                                                   \
    asm volatile("ldmatrix.sync.aligned.m8n8.x4.trans.shared.b16 {%0,%1,%2,%3}, [%4];" \
        : "=r"((r)[0]), "=r"((r)[1]), "=r"((r)[2]), "=r"((r)[3])             \
        : "r"(addr))

#define MMA16816H(c, a, b)                                                   \
    asm volatile("mma.sync.aligned.m16n8k16.row.col.f32.f16.f16.f32 "        \
        "{%0,%1,%2,%3}, {%4,%5,%6,%7}, {%8,%9}, {%0,%1,%2,%3};"              \
        : "+f"((c)[0]), "+f"((c)[1]), "+f"((c)[2]), "+f"((c)[3])             \
        : "r"((a)[0]), "r"((a)[1]), "r"((a)[2]), "r"((a)[3]),                \
          "r"((b)[0]), "r"((b)[1]))

__device__ __forceinline__ uint32_t packh(float a, float b) {
    __half2 t = __floats2half2_rn(a, b);
    return *(uint32_t*)&t;
}

// ---------------------------------------------------------------------------
// Fused prep: RoPE tables | x -> fp16 | transpose Wqkv | transpose Wout
// ---------------------------------------------------------------------------
__global__ __launch_bounds__(256) void prep_kernel(
    const float* __restrict__ x, const float* __restrict__ Wqkv,
    const float* __restrict__ Wout)
{
    __shared__ float t[32][33];
    const int bx = blockIdx.x, tid = threadIdx.x;

    if (bx < 256) {                       // RoPE tables
        int i = bx * 256 + tid;
        int tt = i >> 5, m = i & 31;
        double invf = exp(-(double)(2 * m) * (log(10000.0) / 64.0));
        double ph = (double)tt * invf;
        g_cos[i] = (float)cos(ph);
        g_sin[i] = (float)sin(ph);
        return;
    }
    if (bx < 4352) {                      // x -> fp16
        int i = (bx - 256) * 256 + tid;   // float4 index, n4 = 1M
        float4 v = ((const float4*)x)[i];
        ((uint32_t*)g_xh)[i * 2 + 0] = packh(v.x, v.y);
        ((uint32_t*)g_xh)[i * 2 + 1] = packh(v.z, v.w);
        return;
    }
    // transpose W[K][N] fp32 -> T[N][K] fp16
    const float* W;
    __half* th;
    int N, tile, ntx;
    if (bx < 7424) { W = Wqkv; th = g_wqt; N = QKV_LD;  tile = bx - 4352; ntx = 96; }
    else           { W = Wout; th = g_wot; N = D_MODEL; tile = bx - 7424; ntx = 32; }
    const int K = D_MODEL;
    int n0 = (tile % ntx) * 32, k0 = (tile / ntx) * 32;
    int tx = tid & 31, ty = tid >> 5;
    for (int r = ty; r < 32; r += 8)
        t[r][tx] = W[(size_t)(k0 + r) * N + n0 + tx];
    __syncthreads();
    for (int r = ty; r < 32; r += 8)
        th[(size_t)(n0 + r) * K + k0 + tx] = __float2half_rn(t[tx][r]);
}

// ---------------------------------------------------------------------------
// Single-term fp16 GEMM, K-chunk 64, 3-stage cp.async pipeline,
// ONE barrier per 64-wide chunk (64 MMAs per barrier window),
// B-fragment prefetch (depth 1) inside each 32-half of the chunk.
// C = A[M,K] @ Bt[N,K]^T.
// EPI=0: fp32 C out.  EPI=1: RoPE + log2-scale, fp16 out (QKV path).
// ---------------------------------------------------------------------------
#define GSTR 72
#define TILE_HLV (128 * GSTR)                  /* one 128x64 fp16 tile (halves) */
#define G_STAGE_B (2 * TILE_HLV * 2)           /* 36864 B per stage */
#define G_SMEM3 (3 * G_STAGE_B)                /* 110592 B */

template <int EPI>
__global__ __launch_bounds__(256, 2) void gemm_mma_kernel(
    const __half* __restrict__ Ah, const __half* __restrict__ Bh,
    float* __restrict__ C, __half* __restrict__ Cf, int N, int K)
{
    extern __shared__ __half smg[];
    const uint32_t sbase = smem_u32(smg);

    const int tid = threadIdx.x;
    const int wid = tid >> 5, lid = tid & 31;
    const int wm = (wid & 3) * 32;
    const int wn = (wid >> 2) * 64;

    const size_t aoff0 = (size_t)blockIdx.y * 128 * K;
    const size_t boff0 = (size_t)blockIdx.x * 128 * K;

    uint32_t aAddr[2];
#pragma unroll
    for (int mt = 0; mt < 2; mt++)
        aAddr[mt] = ((wm + mt * 16 + (lid & 15)) * GSTR + (lid >> 4) * 8) * 2;
    uint32_t bAddr[4];
#pragma unroll
    for (int p = 0; p < 4; p++)
        bAddr[p] = ((wn + p * 16 + (lid & 7) + (lid >> 4) * 8) * GSTR
                    + ((lid >> 3) & 1) * 8) * 2;

    const int nchunks = K >> 6;                /* 64-wide chunks */

    auto issue = [&](int c, int st) {
        const __half* srcs[2] = { Ah + aoff0 + c * 64, Bh + boff0 + c * 64 };
        const uint32_t d0 = sbase + st * G_STAGE_B;
#pragma unroll
        for (int tI = 0; tI < 2; tI++) {
#pragma unroll
            for (int it = 0; it < 4; it++) {
                int idx = tid + it * 256;          // 0..1023
                int row = idx >> 3, c8 = (idx & 7) * 8;
                CP16(d0 + (uint32_t)(tI * TILE_HLV + row * GSTR + c8) * 2,
                     srcs[tI] + (size_t)row * K + c8);
            }
        }
        CP_COMMIT();
    };

    float acc[2][8][4] = {};

    issue(0, 0);
    issue(1, 1);
    int st = 0;
    for (int c = 0; c < nchunks; c++) {
        if (c + 1 < nchunks) CP_WAIT1(); else CP_WAIT0();
        __syncthreads();                       // stage c visible; stage of c-1 free
        if (c + 2 < nchunks) issue(c + 2, (st + 2) % 3);

        const uint32_t sAh = sbase + st * G_STAGE_B;
        const uint32_t sBh = sAh + TILE_HLV * 2;

#pragma unroll
        for (int half = 0; half < 2; half++) {
            const uint32_t hb = half * 64;     // 32 halves = 64 bytes

            uint32_t ah[2][2][4];
#pragma unroll
            for (int ks = 0; ks < 2; ks++)
#pragma unroll
                for (int mt = 0; mt < 2; mt++)
                    LDSM_X4(ah[ks][mt], sAh + aAddr[mt] + hb + ks * 32);

            uint32_t bb[2][4];
            LDSM_X4(bb[0], sBh + bAddr[0] + hb);
#pragma unroll
            for (int i = 0; i < 8; i++) {
                const int ks = i >> 2, p = i & 3, cur = i & 1;
                if (i < 7) {
                    const int ni = i + 1;
                    LDSM_X4(bb[cur ^ 1], sBh + bAddr[ni & 3] + hb + (ni >> 2) * 32);
                }
                MMA16816H(acc[0][2 * p],     ah[ks][0], bb[cur]);
                MMA16816H(acc[1][2 * p],     ah[ks][1], bb[cur]);
                MMA16816H(acc[0][2 * p + 1], ah[ks][0], bb[cur] + 2);
                MMA16816H(acc[1][2 * p + 1], ah[ks][1], bb[cur] + 2);
            }
        }
        st = (st + 1 == 3) ? 0 : st + 1;
    }

    const int mbase = blockIdx.y * 128 + wm + (lid >> 2);
    const int nbase = blockIdx.x * 128 + wn + (lid & 3) * 2;
#pragma unroll
    for (int mt = 0; mt < 2; mt++) {
#pragma unroll
        for (int half = 0; half < 2; half++) {
            const int row = mbase + mt * 16 + half * 8;
#pragma unroll
            for (int nt = 0; nt < 8; nt++) {
                const int col = nbase + nt * 8;
                float v0 = acc[mt][nt][2 * half + 0];
                float v1 = acc[mt][nt][2 * half + 1];
                if (EPI == 0) {
                    *(float2*)(C + (size_t)row * N + col) = make_float2(v0, v1);
                } else {
                    if (col < 2048) {                  // rope on q,k
                        int t = row & (T_SEQ - 1);
                        int m0 = col & 31;
                        float c0 = g_cos[t * 32 + m0], s0 = g_sin[t * 32 + m0];
                        float c1 = g_cos[t * 32 + m0 + 1], s1 = g_sin[t * 32 + m0 + 1];
                        float o0 = v0 * c0 - v1 * s0;
                        float o1 = v1 * c1 + v0 * s1;
                        if (col < 1024) { o0 *= QSCALE; o1 *= QSCALE; }
                        v0 = o0; v1 = o1;
                    }
                    *(uint32_t*)(Cf + (size_t)row * N + col) = packh(v0, v1);
                }
            }
        }
    }
}

// ---------------------------------------------------------------------------
// fp16 mma.sync flash attention, base-2 softmax (ex2.approx.f16x2),
// 3-stage cp.async KV pipeline, Q fragments hoisted, K/V fragment prefetch.
// CTA: 128 q-rows x one (b,h). 8 warps x m16. K/V chunks of 64.
// ---------------------------------------------------------------------------
#define QSTR 72
#define Q_ELE (128 * QSTR)
#define KVT (64 * QSTR)
#define KV_STAGE (2 * KVT)
#define ATT_SMEM ((Q_ELE + 3 * KV_STAGE) * 2)   /* 73728 B */

__global__ __launch_bounds__(256, 2) void attn_mma_kernel(
    const __half* __restrict__ qkv, __half* __restrict__ aoh)
{
    extern __shared__ __half smh[];
    const uint32_t sb = smem_u32(smh);
    const int tid = threadIdx.x, wid = tid >> 5, lid = tid & 31;
    const int b = blockIdx.y >> 4, h = blockIdx.y & 15;
    const int q0 = blockIdx.x * 128;
    const size_t rowbase = (size_t)(b * T_SEQ) * QKV_LD;
    const int hc = h * 64;

    auto issue_kv = [&](int s0, int st) {
        const uint32_t d0 = sb + (Q_ELE + st * KV_STAGE) * 2;
#pragma unroll
        for (int i = 0; i < 2; i++) {
            int idx = tid + i * 256;
            int r = idx >> 3, c8 = (idx & 7) * 8;
            size_t gk = rowbase + (size_t)(s0 + r) * QKV_LD + 1024 + hc + c8;
            uint32_t so = (uint32_t)(r * QSTR + c8) * 2;
            CP16(d0 + so,           qkv + gk);          // K
            CP16(d0 + KVT * 2 + so, qkv + gk + 1024);   // V
        }
        CP_COMMIT();
    };

    // Prologue: group0 = Q + KV chunk 0; group1 = KV chunk 1
    {
#pragma unroll
        for (int i = 0; i < 4; i++) {
            int idx = tid + i * 256;
            int r = idx >> 3, c8 = (idx & 7) * 8;
            size_t g = rowbase + (size_t)(q0 + r) * QKV_LD + hc + c8;
            CP16(sb + (uint32_t)(r * QSTR + c8) * 2, qkv + g);
        }
        issue_kv(0, 0);
        issue_kv(64, 1);
    }

    const int wm = wid * 16;
    const uint32_t qAddr = sb + ((wm + (lid & 15)) * QSTR + (lid >> 4) * 8) * 2;
    const uint32_t kRel = (((lid & 7) + (lid >> 4) * 8) * QSTR + ((lid >> 3) & 1) * 8) * 2;
    const uint32_t vRel = ((lid & 15) * QSTR + (lid >> 4) * 8) * 2;

    float o[8][4] = {};
    float mrow[2] = {-INFINITY, -INFINITY};   // log2 domain
    float lrow[2] = {0.f, 0.f};

    // Hoist Q fragments (CP_WAIT1: group0 carrying Q is complete)
    uint32_t qa[4][4];
    {
        CP_WAIT1();
        __syncthreads();
#pragma unroll
        for (int ks = 0; ks < 4; ks++)
            LDSM_X4(qa[ks], qAddr + ks * 32);
    }

    const int nchunks = T_SEQ / 64;
    int st = 0;
    for (int c = 0; c < nchunks; c++) {
        if (c + 1 < nchunks) CP_WAIT1(); else CP_WAIT0();
        __syncthreads();
        if (c + 2 < nchunks) issue_kv((c + 2) * 64, (st + 2) % 3);

        const uint32_t kBase = sb + (Q_ELE + st * KV_STAGE) * 2 + kRel;
        const uint32_t vBase = sb + (Q_ELE + st * KV_STAGE + KVT) * 2 + vRel;

        // S = Q K^T  (S in log2 domain), K-fragment prefetch
        float sc[8][4] = {};
        {
            uint32_t kb[2][4];
            LDSM_X4(kb[0], kBase);
#pragma unroll
            for (int i = 0; i < 16; i++) {
                const int ks = i >> 2, p = i & 3, cur = i & 1;
                if (i < 15) {
                    const int ni = i + 1;
                    LDSM_X4(kb[cur ^ 1],
                            kBase + (ni & 3) * (16 * QSTR * 2) + (ni >> 2) * 32);
                }
                MMA16816H(sc[2 * p],     qa[ks], kb[cur]);
                MMA16816H(sc[2 * p + 1], qa[ks], kb[cur] + 2);
            }
        }

        // Base-2 online softmax, P computed as ex2.approx.f16x2(s - m)
        uint32_t ph[4][4];
#pragma unroll
        for (int hr = 0; hr < 2; hr++) {
            float mx = -INFINITY;
#pragma unroll
            for (int t = 0; t < 8; t++)
                mx = fmaxf(mx, fmaxf(sc[t][2 * hr], sc[t][2 * hr + 1]));
            mx = fmaxf(mx, __shfl_xor_sync(0xffffffffu, mx, 1));
            mx = fmaxf(mx, __shfl_xor_sync(0xffffffffu, mx, 2));
            float mnew = fmaxf(mrow[hr], mx);
            float alpha = exp2f(mrow[hr] - mnew);

            __half2 e[8];
#pragma unroll
            for (int t = 0; t < 8; t++) {
                e[t] = h2exp2(__floats2half2_rn(sc[t][2 * hr] - mnew,
                                                sc[t][2 * hr + 1] - mnew));
                ph[t >> 1][(t & 1) * 2 + hr] = *(uint32_t*)&e[t];
            }
            float rs = 0.f;
#pragma unroll
            for (int t = 0; t < 8; t += 2) {
                float2 f2 = __half22float2(__hadd2(e[t], e[t + 1]));
                rs += f2.x + f2.y;
            }
            rs += __shfl_xor_sync(0xffffffffu, rs, 1);
            rs += __shfl_xor_sync(0xffffffffu, rs, 2);
            lrow[hr] = lrow[hr] * alpha + rs;
            // Warp-uniform skip: when no lane's max moved, alpha==1 for all.
            if (!__all_sync(0xffffffffu, mnew == mrow[hr])) {
#pragma unroll
                for (int t = 0; t < 8; t++) {
                    o[t][2 * hr] *= alpha;
                    o[t][2 * hr + 1] *= alpha;
                }
            }
            mrow[hr] = mnew;
        }

        // O += P V  (V-fragment prefetch)
        {
            uint32_t vb[2][4];
            LDSM_X4_T(vb[0], vBase);
#pragma unroll
            for (int i = 0; i < 16; i++) {
                const int ks = i >> 2, p = i & 3, cur = i & 1;
                if (i < 15) {
                    const int ni = i + 1;
                    LDSM_X4_T(vb[cur ^ 1],
                              vBase + (ni >> 2) * (16 * QSTR * 2) + (ni & 3) * 32);
                }
                MMA16816H(o[2 * p],     ph[ks], vb[cur]);
                MMA16816H(o[2 * p + 1], ph[ks], vb[cur] + 2);
            }
        }
        st = (st + 1 == 3) ? 0 : st + 1;
    }

    // Normalize + fp16 store
#pragma unroll
    for (int hr = 0; hr < 2; hr++) {
        int r = q0 + wm + (lid >> 2) + hr * 8;
        float inv = 1.0f / lrow[hr];
        size_t rowoff = (size_t)(b * T_SEQ + r) * D_MODEL + hc + (lid & 3) * 2;
#pragma unroll
        for (int t = 0; t < 8; t++)
            *(uint32_t*)(aoh + rowoff + t * 8) =
                packh(o[t][2 * hr] * inv, o[t][2 * hr + 1] * inv);
    }
}

// ---------------------------------------------------------------------------
// Launch
// ---------------------------------------------------------------------------
extern "C" void kernel_launch(void* const* d_in, const int* in_sizes, int n_in,
                              void* d_out, int out_size) {
    const float* x    = (const float*)d_in[0];
    const float* Wqkv = (const float*)d_in[1];
    const float* Wout = (const float*)d_in[2];
    float* out = (float*)d_out;

    __half *qkvf, *xh, *aoh, *wq, *wo;
    cudaGetSymbolAddress((void**)&qkvf, g_qkvf);
    cudaGetSymbolAddress((void**)&xh, g_xh);
    cudaGetSymbolAddress((void**)&aoh, g_aoh);
    cudaGetSymbolAddress((void**)&wq, g_wqt);
    cudaGetSymbolAddress((void**)&wo, g_wot);

    cudaFuncSetAttribute((const void*)gemm_mma_kernel<0>,
                         cudaFuncAttributeMaxDynamicSharedMemorySize, G_SMEM3);
    cudaFuncSetAttribute((const void*)gemm_mma_kernel<1>,
                         cudaFuncAttributeMaxDynamicSharedMemorySize, G_SMEM3);
    cudaFuncSetAttribute((const void*)attn_mma_kernel,
                         cudaFuncAttributeMaxDynamicSharedMemorySize, ATT_SMEM);

    // 1. Fused prep: tables | x->fp16 | W transposes
    prep_kernel<<<8448, 256>>>(x, Wqkv, Wout);

    // 2. QKV projection (fp16) + fused RoPE/log2-scale epilogue
    gemm_mma_kernel<1><<<dim3(QKV_LD / 128, M_ROWS / 128), 256, G_SMEM3>>>(
        xh, wq, nullptr, qkvf, QKV_LD, D_MODEL);

    // 3. Attention (fp16 mma.sync flash, base-2 softmax)
    attn_mma_kernel<<<dim3(T_SEQ / 128, B_BATCH * H_HEADS), 256, ATT_SMEM>>>(
        qkvf, aoh);

    // 4. Output projection (fp16)
    gemm_mma_kernel<0><<<dim3(D_MODEL / 128, M_ROWS / 128), 256, G_SMEM3>>>(
        aoh, wo, out, nullptr, D_MODEL, D_MODEL);
}